// round 10
// baseline (speedup 1.0000x reference)
#include <cuda_runtime.h>
#include <cuda_fp16.h>
#include <cstdint>

#define CCH 768
#define NK  192
#define NCHUNK 12
#define NT 256

// smem (bytes), per CTA (2 CTAs/SM):
//  projection: W triple buffer, per buf 25600 (64 k-rows x 200 halves) -> 76800
//  attention overlay @0: KH/QH/VH fp16 [64][72] each 9216 -> 27648 (inside buf0/1, reused after loop)
#define WOFF(b) ((b) * 25600)
#define SMEM_BYTES 76800

__device__ __align__(16) __half g_W[CCH * NK];

__global__ void prep_weights(const float* __restrict__ Wk,
                             const float* __restrict__ Wq,
                             const float* __restrict__ Wv) {
    int i = blockIdx.x * blockDim.x + threadIdx.x;
    if (i >= CCH * NK) return;
    int c = i / NK, n = i % NK;
    const float* W = (n < 64) ? Wk : (n < 128) ? Wq : Wv;
    g_W[i] = __float2half_rn(W[c * 64 + (n & 63)]);
}

__device__ __forceinline__ uint32_t sptr(const void* p) {
    return (uint32_t)__cvta_generic_to_shared(p);
}
__device__ __forceinline__ void ldsm_x4(uint32_t* r, uint32_t addr) {
    asm volatile("ldmatrix.sync.aligned.m8n8.x4.shared.b16 {%0,%1,%2,%3}, [%4];"
                 : "=r"(r[0]), "=r"(r[1]), "=r"(r[2]), "=r"(r[3]) : "r"(addr));
}
__device__ __forceinline__ void ldsm_x4t(uint32_t* r, uint32_t addr) {
    asm volatile("ldmatrix.sync.aligned.m8n8.x4.trans.shared.b16 {%0,%1,%2,%3}, [%4];"
                 : "=r"(r[0]), "=r"(r[1]), "=r"(r[2]), "=r"(r[3]) : "r"(addr));
}
__device__ __forceinline__ void mma16816(float* c, const uint32_t* a, const uint32_t* b) {
    asm volatile("mma.sync.aligned.m16n8k16.row.col.f32.f16.f16.f32 "
                 "{%0,%1,%2,%3}, {%4,%5,%6,%7}, {%8,%9}, {%0,%1,%2,%3};"
                 : "+f"(c[0]), "+f"(c[1]), "+f"(c[2]), "+f"(c[3])
                 : "r"(a[0]), "r"(a[1]), "r"(a[2]), "r"(a[3]), "r"(b[0]), "r"(b[1]));
}
__device__ __forceinline__ void cpasync16(uint32_t d, const void* s) {
    asm volatile("cp.async.cg.shared.global [%0], [%1], 16;" :: "r"(d), "l"(s));
}
__device__ __forceinline__ uint32_t packh2(float a, float b) {
    __half2 h = __floats2half2_rn(a, b);
    return *(uint32_t*)&h;
}

extern "C" __global__ void __launch_bounds__(NT, 2)
head_main(const float* __restrict__ x, float* __restrict__ out) {
    extern __shared__ char smem[];

    const int tid = threadIdx.x;
    const int w = tid >> 5;
    const int lane = tid & 31;

    // -------- issue W chunks 0 and 1 (separate commit groups)
#pragma unroll
    for (int j = 0; j < 6; j++) {
        int idx = j * NT + tid;                 // 1536: 64 k-rows x 24 16B-segs
        int row = idx / 24, c16 = (idx % 24) * 8;
        cpasync16(sptr(smem + WOFF(0)) + (uint32_t)(row * 400 + c16 * 2),
                  g_W + row * NK + c16);
    }
    asm volatile("cp.async.commit_group;" ::: "memory");
#pragma unroll
    for (int j = 0; j < 6; j++) {
        int idx = j * NT + tid;
        int row = idx / 24, c16 = (idx % 24) * 8;
        cpasync16(sptr(smem + WOFF(1)) + (uint32_t)(row * 400 + c16 * 2),
                  g_W + (size_t)64 * NK + row * NK + c16);
    }
    asm volatile("cp.async.commit_group;" ::: "memory");

    // warp grid 2x4: M32 x N48 per warp
    const int mwarp = w & 1;
    const int nwarp = w >> 1;
    const int g = lane >> 2;          // row within 8-row group
    const int t2 = (lane & 3) * 2;    // col pair

    float acc[12][4];
#pragma unroll
    for (int jt = 0; jt < 12; jt++)
#pragma unroll
        for (int r = 0; r < 4; r++) acc[jt][r] = 0.0f;

    // A direct-gmem base: row mwarp*32 + g, col t2 of this block's x tile
    const float* xa = x + (size_t)blockIdx.x * 64 * CCH + (mwarp * 32 + g) * CCH + t2;
    const int b_base = nwarp * 48 + (lane >> 4) * 8;
    const int b_row = lane & 15;

#pragma unroll 1
    for (int kc = 0; kc < NCHUNK; kc++) {
        const int buf = kc % 3;

        // -------- A fragments for chunk kc: 32 LDG.64 + 32 cvt, all independent
        uint32_t af[2][4][4];  // [mt][ks][frag]
#pragma unroll
        for (int mt = 0; mt < 2; mt++) {
            const float* xr = xa + mt * 16 * CCH + kc * 64;
#pragma unroll
            for (int ks = 0; ks < 4; ks++) {
                float2 f0 = *(const float2*)(xr + ks * 16);
                float2 f1 = *(const float2*)(xr + 8 * CCH + ks * 16);
                float2 f2 = *(const float2*)(xr + ks * 16 + 8);
                float2 f3 = *(const float2*)(xr + 8 * CCH + ks * 16 + 8);
                af[mt][ks][0] = packh2(f0.x, f0.y);
                af[mt][ks][1] = packh2(f1.x, f1.y);
                af[mt][ks][2] = packh2(f2.x, f2.y);
                af[mt][ks][3] = packh2(f3.x, f3.y);
            }
        }

        // -------- W[kc] ready + safe to rotate buffer (kc+2)%3
        if (kc + 1 < NCHUNK) asm volatile("cp.async.wait_group 1;" ::: "memory");
        else                 asm volatile("cp.async.wait_group 0;" ::: "memory");
        __syncthreads();   // W[kc] visible to all warps; all MMA of kc-1 drained

        if (kc + 2 < NCHUNK) {
            const size_t gk = (size_t)(kc + 2) * 64 * NK;
            const uint32_t db = sptr(smem + WOFF((kc + 2) % 3));
#pragma unroll
            for (int j = 0; j < 6; j++) {
                int idx = j * NT + tid;
                int row = idx / 24, c16 = (idx % 24) * 8;
                cpasync16(db + (uint32_t)(row * 400 + c16 * 2), g_W + gk + row * NK + c16);
            }
            asm volatile("cp.async.commit_group;" ::: "memory");
        }

        // -------- MMA from W[buf]
        const __half* WHs = (const __half*)(smem + WOFF(buf));
#pragma unroll
        for (int ks = 0; ks < 4; ks++) {
            const int br = (ks * 16 + b_row) * 200 + b_base;
#pragma unroll
            for (int j = 0; j < 3; j++) {
                uint32_t bh[4];
                ldsm_x4t(bh, sptr(WHs + br + j * 16));
                mma16816(acc[0 * 6 + 2 * j],     af[0][ks], bh);
                mma16816(acc[0 * 6 + 2 * j + 1], af[0][ks], bh + 2);
                mma16816(acc[1 * 6 + 2 * j],     af[1][ks], bh);
                mma16816(acc[1 * 6 + 2 * j + 1], af[1][ks], bh + 2);
            }
        }
    }
    __syncthreads();  // projection done; smem repurposed

    // -------- fragments -> KH/QH/VH (fp16, [64][72])
    __half* KH = (__half*)smem;
    __half* QH = KH + 4608;
    __half* VH = QH + 4608;
    {
#pragma unroll
        for (int mt = 0; mt < 2; mt++) {
            const int tr = mwarp * 32 + mt * 16 + g;
#pragma unroll
            for (int jn = 0; jn < 6; jn++) {
                int col = nwarp * 48 + jn * 8 + t2;
                __half* dst = (col < 64) ? (KH + col) : (col < 128) ? (QH + col - 64) : (VH + col - 128);
                const float* a = acc[mt * 6 + jn];
                *(uint32_t*)(dst + tr * 72)       = packh2(a[0], a[1]);
                *(uint32_t*)(dst + (tr + 8) * 72) = packh2(a[2], a[3]);
            }
        }
    }
    __syncthreads();

    // -------- attention via MMA: warps 0-3, strip of 16 rows each
    if (w < 4) {
        const int row0 = w * 16 + g;
        const int row1 = row0 + 8;

        // S = Q @ K^T
        float sc[8][4];
#pragma unroll
        for (int nj = 0; nj < 8; nj++)
#pragma unroll
            for (int r = 0; r < 4; r++) sc[nj][r] = 0.0f;

        const int a_q = (w * 16 + (lane & 15)) * 72 + (lane >> 4) * 8;
        const int kb_row = (lane & 7) + ((lane >> 4) << 3);
        const int kb_off = ((lane >> 3) & 1) * 8;
#pragma unroll
        for (int kk = 0; kk < 4; kk++) {
            uint32_t aq[4];
            ldsm_x4(aq, sptr(QH + a_q + kk * 16));
#pragma unroll
            for (int jn = 0; jn < 4; jn++) {
                uint32_t bk[4];
                ldsm_x4(bk, sptr(KH + (jn * 16 + kb_row) * 72 + kk * 16 + kb_off));
                mma16816(sc[2 * jn],     aq, bk);
                mma16816(sc[2 * jn + 1], aq, bk + 2);
            }
        }

        // scale + causal mask + softmax
        float m0 = -3.0e38f, m1 = -3.0e38f;
#pragma unroll
        for (int nj = 0; nj < 8; nj++) {
#pragma unroll
            for (int e = 0; e < 2; e++) {
                int col = 8 * nj + t2 + e;
                float v0 = sc[nj][e] * 0.125f;
                float v1 = sc[nj][2 + e] * 0.125f;
                v0 = (col <= row0) ? v0 : -3.0e38f;
                v1 = (col <= row1) ? v1 : -3.0e38f;
                sc[nj][e] = v0;
                sc[nj][2 + e] = v1;
                m0 = fmaxf(m0, v0);
                m1 = fmaxf(m1, v1);
            }
        }
        m0 = fmaxf(m0, __shfl_xor_sync(0xffffffffu, m0, 1));
        m0 = fmaxf(m0, __shfl_xor_sync(0xffffffffu, m0, 2));
        m1 = fmaxf(m1, __shfl_xor_sync(0xffffffffu, m1, 1));
        m1 = fmaxf(m1, __shfl_xor_sync(0xffffffffu, m1, 2));
        float s0 = 0.0f, s1 = 0.0f;
#pragma unroll
        for (int nj = 0; nj < 8; nj++) {
#pragma unroll
            for (int e = 0; e < 2; e++) {
                float e0 = __expf(sc[nj][e] - m0);
                float e1 = __expf(sc[nj][2 + e] - m1);
                sc[nj][e] = e0;
                sc[nj][2 + e] = e1;
                s0 += e0;
                s1 += e1;
            }
        }
        s0 += __shfl_xor_sync(0xffffffffu, s0, 1);
        s0 += __shfl_xor_sync(0xffffffffu, s0, 2);
        s1 += __shfl_xor_sync(0xffffffffu, s1, 1);
        s1 += __shfl_xor_sync(0xffffffffu, s1, 2);
        const float i0v = 1.0f / s0, i1v = 1.0f / s1;
#pragma unroll
        for (int nj = 0; nj < 8; nj++) {
            sc[nj][0] *= i0v; sc[nj][1] *= i0v;
            sc[nj][2] *= i1v; sc[nj][3] *= i1v;
        }

        // out = P @ V : P regs -> A fragments; B = V via ldsm_x4t
        float oc[8][4];
#pragma unroll
        for (int nj = 0; nj < 8; nj++)
#pragma unroll
            for (int r = 0; r < 4; r++) oc[nj][r] = 0.0f;

        const int v_row = lane & 15;
        const int v_off = (lane >> 4) * 8;
#pragma unroll 1
        for (int kk = 0; kk <= w; kk++) {   // tokens > 16w+15 have P == 0 exactly
            uint32_t pa[4];
            pa[0] = packh2(sc[2 * kk][0],     sc[2 * kk][1]);
            pa[1] = packh2(sc[2 * kk][2],     sc[2 * kk][3]);
            pa[2] = packh2(sc[2 * kk + 1][0], sc[2 * kk + 1][1]);
            pa[3] = packh2(sc[2 * kk + 1][2], sc[2 * kk + 1][3]);
            const __half* vb = VH + (16 * kk + v_row) * 72 + v_off;
#pragma unroll
            for (int jn = 0; jn < 4; jn++) {
                uint32_t bv[4];
                ldsm_x4t(bv, sptr(vb + jn * 16));
                mma16816(oc[2 * jn],     pa, bv);
                mma16816(oc[2 * jn + 1], pa, bv + 2);
            }
        }

        // store directly to gmem
        float* ob = out + (size_t)blockIdx.x * 4096;
#pragma unroll
        for (int nj = 0; nj < 8; nj++) {
            int col = 8 * nj + t2;
            *(float2*)(ob + row0 * 64 + col) = make_float2(oc[nj][0], oc[nj][1]);
            *(float2*)(ob + row1 * 64 + col) = make_float2(oc[nj][2], oc[nj][3]);
        }
    }
}

extern "C" void kernel_launch(void* const* d_in, const int* in_sizes, int n_in,
                              void* d_out, int out_size) {
    const float* x  = (const float*)d_in[0];
    const float* Wk = (const float*)d_in[1];
    const float* Wq = (const float*)d_in[2];
    const float* Wv = (const float*)d_in[3];
    float* out = (float*)d_out;

    cudaFuncSetAttribute(head_main, cudaFuncAttributeMaxDynamicSharedMemorySize, SMEM_BYTES);

    prep_weights<<<(CCH * NK + 255) / 256, 256>>>(Wk, Wq, Wv);
    head_main<<<2048, NT, SMEM_BYTES>>>(x, out);
}